// round 1
// baseline (speedup 1.0000x reference)
#include <cuda_runtime.h>
#include <cuda_bf16.h>
#include <cstdint>

#define SM_STRIDE 136            // bf16 elems per smem row (128 + 8 pad -> conflict-free ldmatrix)
#define TILE_B    (128 * SM_STRIDE * 2)

// smem byte offsets
#define XHI_OFF   0
#define XLO_OFF   (XHI_OFF + TILE_B)
#define WHI_OFF   (XLO_OFF + TILE_B)
#define WLO_OFF   (WHI_OFF + TILE_B)
#define XN2_OFF   (WLO_OFF + TILE_B)     // float[128]
#define HV_OFF    (XN2_OFF + 512)        // float[128]
#define RSQ_OFF   (HV_OFF  + 512)        // float[2][128]
#define RDH_OFF   (RSQ_OFF + 1024)       // float[2][128]
#define PA_OFF    (RDH_OFF + 1024)       // float[128]
#define PB_OFF    (PA_OFF  + 512)
#define LL_OFF    (PB_OFF  + 512)
#define FS_OFF    (LL_OFF  + 512)
#define SC_OFF    (FS_OFF  + 512)        // float[4]
#define SMEM_BYTES (SC_OFF + 16)

#define MINN  1e-15f
#define MAXN  0.996f                      // (1 - 4e-3)/sqrt(c), c=1
#define ATLIM (1.0f - 1e-7f)

__device__ __forceinline__ unsigned int bfu(__nv_bfloat16 h) {
    return (unsigned int)*reinterpret_cast<unsigned short*>(&h);
}

#define LDSM4(R, addr)                                                        \
    asm volatile("ldmatrix.sync.aligned.m8n8.x4.shared.b16 {%0,%1,%2,%3}, [%4];" \
                 : "=r"((R)[0]), "=r"((R)[1]), "=r"((R)[2]), "=r"((R)[3])     \
                 : "r"(addr) : "memory")

__device__ __forceinline__ void mma16816(float* d, const uint32_t* a, const uint32_t* b) {
    asm volatile(
        "mma.sync.aligned.m16n8k16.row.col.f32.bf16.bf16.f32 "
        "{%0,%1,%2,%3}, {%4,%5,%6,%7}, {%8,%9}, {%0,%1,%2,%3};"
        : "+f"(d[0]), "+f"(d[1]), "+f"(d[2]), "+f"(d[3])
        : "r"(a[0]), "r"(a[1]), "r"(a[2]), "r"(a[3]), "r"(b[0]), "r"(b[1]));
}

__device__ __forceinline__ float artanh_c(float x) {
    float xc = fminf(x, ATLIM);
    return 0.5f * (log1pf(xc) - log1pf(-xc));
}

__global__ void __launch_bounds__(256, 1)
blinear_fused(const float* __restrict__ X, const float* __restrict__ W,
              const float* __restrict__ B, float* __restrict__ OUT)
{
    extern __shared__ char smem[];
    __nv_bfloat16* xs_hi = (__nv_bfloat16*)(smem + XHI_OFF);
    __nv_bfloat16* xs_lo = (__nv_bfloat16*)(smem + XLO_OFF);
    __nv_bfloat16* ws_hi = (__nv_bfloat16*)(smem + WHI_OFF);
    __nv_bfloat16* ws_lo = (__nv_bfloat16*)(smem + WLO_OFF);
    float* xn2   = (float*)(smem + XN2_OFF);
    float* hvec  = (float*)(smem + HV_OFF);
    float* red_sq= (float*)(smem + RSQ_OFF);
    float* red_dh= (float*)(smem + RDH_OFF);
    float* PA    = (float*)(smem + PA_OFF);
    float* PB    = (float*)(smem + PB_OFF);
    float* LLs   = (float*)(smem + LL_OFF);
    float* FSs   = (float*)(smem + FS_OFF);
    float* SC    = (float*)(smem + SC_OFF);

    const int tid  = threadIdx.x;
    const int lane = tid & 31;
    const int w    = tid >> 5;
    const int wm   = w & 3;      // M warp (0..3): rows 32*wm..
    const int wn   = w >> 2;     // N warp (0..1): cols 64*wn..
    const int tq   = lane & 3;
    const int q    = lane >> 2;
    const long blockRow = (long)blockIdx.x * 128;

    // ---- load + bf16 split: x tile (128x128) and W (128x128) ----
    #pragma unroll
    for (int i = 0; i < 16; ++i) {
        int row = i * 8 + w;
        // x
        float4 v = *(const float4*)(X + (size_t)(blockRow + row) * 128 + lane * 4);
        float sq = v.x*v.x + v.y*v.y + v.z*v.z + v.w*v.w;
        #pragma unroll
        for (int o = 16; o; o >>= 1) sq += __shfl_xor_sync(0xffffffffu, sq, o);
        if (lane == 0) xn2[row] = sq;
        {
            __nv_bfloat16 h0 = __float2bfloat16(v.x), h1 = __float2bfloat16(v.y);
            __nv_bfloat16 h2 = __float2bfloat16(v.z), h3 = __float2bfloat16(v.w);
            __nv_bfloat16 l0 = __float2bfloat16(v.x - __bfloat162float(h0));
            __nv_bfloat16 l1 = __float2bfloat16(v.y - __bfloat162float(h1));
            __nv_bfloat16 l2 = __float2bfloat16(v.z - __bfloat162float(h2));
            __nv_bfloat16 l3 = __float2bfloat16(v.w - __bfloat162float(h3));
            uint2 ph, pl;
            ph.x = bfu(h0) | (bfu(h1) << 16); ph.y = bfu(h2) | (bfu(h3) << 16);
            pl.x = bfu(l0) | (bfu(l1) << 16); pl.y = bfu(l2) | (bfu(l3) << 16);
            *(uint2*)(xs_hi + row * SM_STRIDE + lane * 4) = ph;
            *(uint2*)(xs_lo + row * SM_STRIDE + lane * 4) = pl;
        }
        // W
        float4 wv = *(const float4*)(W + (size_t)row * 128 + lane * 4);
        {
            __nv_bfloat16 h0 = __float2bfloat16(wv.x), h1 = __float2bfloat16(wv.y);
            __nv_bfloat16 h2 = __float2bfloat16(wv.z), h3 = __float2bfloat16(wv.w);
            __nv_bfloat16 l0 = __float2bfloat16(wv.x - __bfloat162float(h0));
            __nv_bfloat16 l1 = __float2bfloat16(wv.y - __bfloat162float(h1));
            __nv_bfloat16 l2 = __float2bfloat16(wv.z - __bfloat162float(h2));
            __nv_bfloat16 l3 = __float2bfloat16(wv.w - __bfloat162float(h3));
            uint2 ph, pl;
            ph.x = bfu(h0) | (bfu(h1) << 16); ph.y = bfu(h2) | (bfu(h3) << 16);
            pl.x = bfu(l0) | (bfu(l1) << 16); pl.y = bfu(l2) | (bfu(l3) << 16);
            *(uint2*)(ws_hi + row * SM_STRIDE + lane * 4) = ph;
            *(uint2*)(ws_lo + row * SM_STRIDE + lane * 4) = pl;
        }
    }

    // ---- hyp_bias h = proj(expmap0(b)) (warp 0) ----
    if (w == 0) {
        float4 bv = *(const float4*)(B + lane * 4);
        float sq = bv.x*bv.x + bv.y*bv.y + bv.z*bv.z + bv.w*bv.w;
        #pragma unroll
        for (int o = 16; o; o >>= 1) sq += __shfl_xor_sync(0xffffffffu, sq, o);
        float bn2 = sq;
        float bn  = fmaxf(sqrtf(bn2), MINN);
        float th  = tanhf(bn);
        float hs  = th / bn;                 // h = hs * b
        float hn  = hs * sqrtf(bn2);         // |h|
        float pn  = fmaxf(hn, MINN);
        if (pn > MAXN) hs *= MAXN / pn;      // proj
        float y2  = hs * hs * bn2;           // |h|^2 after proj
        if (lane == 0) SC[0] = y2;
        *(float4*)(hvec + lane * 4) =
            make_float4(hs*bv.x, hs*bv.y, hs*bv.z, hs*bv.w);
    }
    __syncthreads();

    // ---- MMA: mx = x @ W^T via bf16x2 split (hi*hi + hi*lo + lo*hi) ----
    uint32_t s_xhi = (uint32_t)__cvta_generic_to_shared(xs_hi);
    uint32_t s_xlo = (uint32_t)__cvta_generic_to_shared(xs_lo);
    uint32_t s_whi = (uint32_t)__cvta_generic_to_shared(ws_hi);
    uint32_t s_wlo = (uint32_t)__cvta_generic_to_shared(ws_lo);

    const int a_r = lane & 15;
    const int a_c = (lane >> 4) * 8;
    const uint32_t aoff0 = (uint32_t)(((32*wm + a_r) * SM_STRIDE + a_c) * 2);
    const uint32_t aoff1 = aoff0 + 16 * SM_STRIDE * 2;

    const int bg  = lane >> 3;
    const int b_n = ((bg >> 1) << 3) + (lane & 7);
    const int b_k = (bg & 1) * 8;
    uint32_t boff[4];
    #pragma unroll
    for (int p = 0; p < 4; ++p)
        boff[p] = (uint32_t)(((64*wn + 16*p + b_n) * SM_STRIDE + b_k) * 2);

    float acc[2][8][4];
    #pragma unroll
    for (int mt = 0; mt < 2; ++mt)
        #pragma unroll
        for (int nt = 0; nt < 8; ++nt)
            #pragma unroll
            for (int r = 0; r < 4; ++r) acc[mt][nt][r] = 0.f;

    #pragma unroll
    for (int k = 0; k < 8; ++k) {
        const uint32_t kb = k * 32;
        uint32_t ah0[4], ah1[4], al0[4], al1[4];
        LDSM4(ah0, s_xhi + aoff0 + kb);
        LDSM4(ah1, s_xhi + aoff1 + kb);
        LDSM4(al0, s_xlo + aoff0 + kb);
        LDSM4(al1, s_xlo + aoff1 + kb);
        uint32_t bh[4][4], bl[4][4];
        #pragma unroll
        for (int p = 0; p < 4; ++p) {
            LDSM4(bh[p], s_whi + boff[p] + kb);
            LDSM4(bl[p], s_wlo + boff[p] + kb);
        }
        #pragma unroll
        for (int nt = 0; nt < 8; ++nt) {
            const int p = nt >> 1, o = (nt & 1) * 2;
            mma16816(acc[0][nt], ah0, &bh[p][o]);
            mma16816(acc[1][nt], ah1, &bh[p][o]);
            mma16816(acc[0][nt], ah0, &bl[p][o]);
            mma16816(acc[1][nt], ah1, &bl[p][o]);
            mma16816(acc[0][nt], al0, &bh[p][o]);
            mma16816(acc[1][nt], al1, &bh[p][o]);
        }
    }

    // preload h slice for this warp's columns
    float hv[8][2];
    #pragma unroll
    for (int nt = 0; nt < 8; ++nt) {
        int c = 64*wn + 8*nt + 2*tq;
        hv[nt][0] = hvec[c]; hv[nt][1] = hvec[c + 1];
    }

    // ---- phase 1: per-row sum(mx^2), sum(mx*h) ----
    #pragma unroll
    for (int mt = 0; mt < 2; ++mt)
        #pragma unroll
        for (int rh = 0; rh < 2; ++rh) {
            float sq = 0.f, dh = 0.f;
            #pragma unroll
            for (int nt = 0; nt < 8; ++nt) {
                float v0 = acc[mt][nt][2*rh], v1 = acc[mt][nt][2*rh + 1];
                sq = fmaf(v0, v0, fmaf(v1, v1, sq));
                dh = fmaf(v0, hv[nt][0], fmaf(v1, hv[nt][1], dh));
            }
            sq += __shfl_xor_sync(0xffffffffu, sq, 1);
            sq += __shfl_xor_sync(0xffffffffu, sq, 2);
            dh += __shfl_xor_sync(0xffffffffu, dh, 1);
            dh += __shfl_xor_sync(0xffffffffu, dh, 2);
            if (tq == 0) {
                int r = 32*wm + 16*mt + 8*rh + q;
                red_sq[wn*128 + r] = sq;
                red_dh[wn*128 + r] = dh;
            }
        }
    __syncthreads();

    // ---- per-row scalar chain ----
    if (tid < 128) {
        int r = tid;
        float S2 = red_sq[r] + red_sq[128 + r];
        float D  = red_dh[r] + red_dh[128 + r];
        float y2 = SC[0];
        float xn  = fmaxf(sqrtf(xn2[r]), MINN);
        float mxn = fmaxf(sqrtf(S2), MINN);
        float atx = artanh_c(xn);
        float r1  = tanhf(mxn / xn * atx);
        float scale1 = r1 / mxn;                 // res = scale1 * mx
        float resn = r1;
        float pn = fmaxf(resn, MINN);            // proj
        if (pn > MAXN) { scale1 *= MAXN / pn; resn = MAXN; }
        float x2 = resn * resn;
        float xy = scale1 * D;                   // <res, h>
        float num1 = 1.f + 2.f*xy + y2;
        float den  = fmaxf(1.f + 2.f*xy + x2*y2, MINN);
        float aC = num1 / den;
        float bC = (1.f - x2) / den;             // out2 = aC*res + bC*h
        float o2n2 = aC*aC*x2 + 2.f*aC*bC*xy + bC*bC*y2;
        float o2n  = sqrtf(fmaxf(o2n2, 0.f));
        float g = 1.f;
        float pn2 = fmaxf(o2n, MINN);            // proj
        if (pn2 > MAXN) { g = MAXN / pn2; pn2 = MAXN; }
        float Lr = artanh_c(pn2) / pn2;          // logmap0 factor
        PA[r]  = g * aC * scale1;                // multiplier on mx
        PB[r]  = g * bC;                         // multiplier on h
        LLs[r] = Lr;
    }
    __syncthreads();

    // ---- phase 2: val = Pa*mx + Pb*h ; sum(max(val,0)^2) ----
    #pragma unroll
    for (int mt = 0; mt < 2; ++mt)
        #pragma unroll
        for (int rh = 0; rh < 2; ++rh) {
            int rl = 32*wm + 16*mt + 8*rh + q;
            float pa = PA[rl], pb = PB[rl];
            float ps = 0.f;
            #pragma unroll
            for (int nt = 0; nt < 8; ++nt) {
                float v0 = fmaf(pa, acc[mt][nt][2*rh],     pb * hv[nt][0]);
                float v1 = fmaf(pa, acc[mt][nt][2*rh + 1], pb * hv[nt][1]);
                acc[mt][nt][2*rh]     = v0;
                acc[mt][nt][2*rh + 1] = v1;
                float p0 = fmaxf(v0, 0.f), p1 = fmaxf(v1, 0.f);
                ps = fmaf(p0, p0, fmaf(p1, p1, ps));
            }
            ps += __shfl_xor_sync(0xffffffffu, ps, 1);
            ps += __shfl_xor_sync(0xffffffffu, ps, 2);
            if (tq == 0) red_sq[wn*128 + rl] = ps;
        }
    __syncthreads();

    // ---- phase 3: expmap0 + final proj scale ----
    if (tid < 128) {
        int r = tid;
        float ps = red_sq[r] + red_sq[128 + r];
        float P  = sqrtf(fmaxf(ps, 0.f));
        float Lr = LLs[r];
        float un = fmaxf(Lr * P, MINN);
        float th = tanhf(un);
        float f  = th / un * Lr;
        if (th > MAXN) f *= MAXN / th;           // final proj
        FSs[r] = f;
    }
    __syncthreads();

    // ---- store: out = fs * max(val, 0) ----
    #pragma unroll
    for (int mt = 0; mt < 2; ++mt)
        #pragma unroll
        for (int rh = 0; rh < 2; ++rh) {
            int rl = 32*wm + 16*mt + 8*rh + q;
            float fsv = FSs[rl];
            float* outp = OUT + (size_t)(blockRow + rl) * 128 + 64*wn + 2*tq;
            #pragma unroll
            for (int nt = 0; nt < 8; ++nt) {
                float2 o;
                o.x = fsv * fmaxf(acc[mt][nt][2*rh],     0.f);
                o.y = fsv * fmaxf(acc[mt][nt][2*rh + 1], 0.f);
                *(float2*)(outp + 8*nt) = o;
            }
        }
}

extern "C" void kernel_launch(void* const* d_in, const int* in_sizes, int n_in,
                              void* d_out, int out_size) {
    const float* x = (const float*)d_in[0];
    const float* W = (const float*)d_in[1];
    const float* b = (const float*)d_in[2];
    float* out = (float*)d_out;

    int nRows = in_sizes[0] / 128;       // 524288
    int grid  = nRows / 128;             // 4096

    cudaFuncSetAttribute(blinear_fused,
                         cudaFuncAttributeMaxDynamicSharedMemorySize, SMEM_BYTES);
    blinear_fused<<<grid, 256, SMEM_BYTES>>>(x, W, b, out);
}

// round 2
// speedup vs baseline: 1.3170x; 1.3170x over previous
#include <cuda_runtime.h>
#include <cuda_bf16.h>
#include <cstdint>

#define SM_STRIDE 136            // bf16 elems per smem row (conflict-free ldmatrix)
#define XTILE_B   (64  * SM_STRIDE * 2)
#define WTILE_B   (128 * SM_STRIDE * 2)

// smem byte offsets
#define XHI_OFF   0
#define XLO_OFF   (XHI_OFF + XTILE_B)
#define WHI_OFF   (XLO_OFF + XTILE_B)
#define WLO_OFF   (WHI_OFF + WTILE_B)
#define XN2_OFF   (WLO_OFF + WTILE_B)    // float[64]
#define HV_OFF    (XN2_OFF + 256)        // float[128]
#define RSQ_OFF   (HV_OFF  + 512)        // float[4][64]
#define RDH_OFF   (RSQ_OFF + 1024)       // float[4][64]
#define PA_OFF    (RDH_OFF + 1024)       // float[64]
#define PB_OFF    (PA_OFF  + 256)
#define LL_OFF    (PB_OFF  + 256)
#define FS_OFF    (LL_OFF  + 256)
#define SC_OFF    (FS_OFF  + 256)        // float[4]
#define SMEM_BYTES (SC_OFF + 16)         // ~108.3 KB -> 2 CTAs/SM

#define MINN  1e-15f
#define MAXN  0.996f
#define ATLIM (1.0f - 1e-7f)

__device__ __forceinline__ unsigned int bfu(__nv_bfloat16 h) {
    return (unsigned int)*reinterpret_cast<unsigned short*>(&h);
}

#define LDSM4(R, addr)                                                        \
    asm volatile("ldmatrix.sync.aligned.m8n8.x4.shared.b16 {%0,%1,%2,%3}, [%4];" \
                 : "=r"((R)[0]), "=r"((R)[1]), "=r"((R)[2]), "=r"((R)[3])     \
                 : "r"(addr) : "memory")

__device__ __forceinline__ void mma16816(float* d, const uint32_t* a, const uint32_t* b) {
    asm volatile(
        "mma.sync.aligned.m16n8k16.row.col.f32.bf16.bf16.f32 "
        "{%0,%1,%2,%3}, {%4,%5,%6,%7}, {%8,%9}, {%0,%1,%2,%3};"
        : "+f"(d[0]), "+f"(d[1]), "+f"(d[2]), "+f"(d[3])
        : "r"(a[0]), "r"(a[1]), "r"(a[2]), "r"(a[3]), "r"(b[0]), "r"(b[1]));
}

__device__ __forceinline__ float artanh_c(float x) {
    float xc = fminf(x, ATLIM);
    return 0.5f * (log1pf(xc) - log1pf(-xc));
}

__global__ void __launch_bounds__(256, 2)
blinear_fused(const float* __restrict__ X, const float* __restrict__ W,
              const float* __restrict__ B, float* __restrict__ OUT, int nTiles)
{
    extern __shared__ char smem[];
    __nv_bfloat16* xs_hi = (__nv_bfloat16*)(smem + XHI_OFF);
    __nv_bfloat16* xs_lo = (__nv_bfloat16*)(smem + XLO_OFF);
    __nv_bfloat16* ws_hi = (__nv_bfloat16*)(smem + WHI_OFF);
    __nv_bfloat16* ws_lo = (__nv_bfloat16*)(smem + WLO_OFF);
    float* xn2   = (float*)(smem + XN2_OFF);
    float* hvec  = (float*)(smem + HV_OFF);
    float* red_sq= (float*)(smem + RSQ_OFF);
    float* red_dh= (float*)(smem + RDH_OFF);
    float* PA    = (float*)(smem + PA_OFF);
    float* PB    = (float*)(smem + PB_OFF);
    float* LLs   = (float*)(smem + LL_OFF);
    float* FSs   = (float*)(smem + FS_OFF);
    float* SC    = (float*)(smem + SC_OFF);

    const int tid  = threadIdx.x;
    const int lane = tid & 31;
    const int w    = tid >> 5;
    const int wm   = w & 1;      // M warp (0..1): rows 32*wm
    const int wn   = w >> 1;     // N warp (0..3): cols 32*wn
    const int tq   = lane & 3;
    const int q    = lane >> 2;

    // ---- once per CTA: convert W (128x128) to bf16 hi/lo in smem ----
    #pragma unroll
    for (int j = 0; j < 16; ++j) {
        int row = j * 8 + w;
        float4 wv = *(const float4*)(W + (size_t)row * 128 + lane * 4);
        __nv_bfloat16 h0 = __float2bfloat16(wv.x), h1 = __float2bfloat16(wv.y);
        __nv_bfloat16 h2 = __float2bfloat16(wv.z), h3 = __float2bfloat16(wv.w);
        __nv_bfloat16 l0 = __float2bfloat16(wv.x - __bfloat162float(h0));
        __nv_bfloat16 l1 = __float2bfloat16(wv.y - __bfloat162float(h1));
        __nv_bfloat16 l2 = __float2bfloat16(wv.z - __bfloat162float(h2));
        __nv_bfloat16 l3 = __float2bfloat16(wv.w - __bfloat162float(h3));
        uint2 ph, pl;
        ph.x = bfu(h0) | (bfu(h1) << 16); ph.y = bfu(h2) | (bfu(h3) << 16);
        pl.x = bfu(l0) | (bfu(l1) << 16); pl.y = bfu(l2) | (bfu(l3) << 16);
        *(uint2*)(ws_hi + row * SM_STRIDE + lane * 4) = ph;
        *(uint2*)(ws_lo + row * SM_STRIDE + lane * 4) = pl;
    }

    // ---- once per CTA: hyp_bias h = proj(expmap0(b)) (warp 0) ----
    if (w == 0) {
        float4 bv = *(const float4*)(B + lane * 4);
        float sq = bv.x*bv.x + bv.y*bv.y + bv.z*bv.z + bv.w*bv.w;
        #pragma unroll
        for (int o = 16; o; o >>= 1) sq += __shfl_xor_sync(0xffffffffu, sq, o);
        float bn2 = sq;
        float bn  = fmaxf(sqrtf(bn2), MINN);
        float th  = tanhf(bn);
        float hs  = th / bn;
        float hn  = hs * sqrtf(bn2);
        float pn  = fmaxf(hn, MINN);
        if (pn > MAXN) hs *= MAXN / pn;
        float y2  = hs * hs * bn2;
        if (lane == 0) SC[0] = y2;
        *(float4*)(hvec + lane * 4) =
            make_float4(hs*bv.x, hs*bv.y, hs*bv.z, hs*bv.w);
    }
    __syncthreads();

    // preload h slice for this warp's columns (constant across tiles)
    float hv[4][2];
    #pragma unroll
    for (int nt = 0; nt < 4; ++nt) {
        int c = 32*wn + 8*nt + 2*tq;
        hv[nt][0] = hvec[c]; hv[nt][1] = hvec[c + 1];
    }

    // fragment smem addresses (constant)
    uint32_t s_xhi = (uint32_t)__cvta_generic_to_shared(xs_hi);
    uint32_t s_xlo = (uint32_t)__cvta_generic_to_shared(xs_lo);
    uint32_t s_whi = (uint32_t)__cvta_generic_to_shared(ws_hi);
    uint32_t s_wlo = (uint32_t)__cvta_generic_to_shared(ws_lo);

    const int a_r = lane & 15;
    const int a_c = (lane >> 4) * 8;
    const uint32_t aoff0 = (uint32_t)(((32*wm + a_r) * SM_STRIDE + a_c) * 2);
    const uint32_t aoff1 = aoff0 + 16 * SM_STRIDE * 2;

    const int bg  = lane >> 3;
    const int b_n = ((bg >> 1) << 3) + (lane & 7);
    const int b_k = (bg & 1) * 8;
    uint32_t boff[2];
    #pragma unroll
    for (int p = 0; p < 2; ++p)
        boff[p] = (uint32_t)(((32*wn + 16*p + b_n) * SM_STRIDE + b_k) * 2);

    // ================= persistent tile loop =================
    for (int tile = blockIdx.x; tile < nTiles; tile += gridDim.x) {
        const size_t blockRow = (size_t)tile * 64;

        // ---- load x tile (64x128), row norms, bf16-split to smem ----
        #pragma unroll
        for (int j = 0; j < 8; ++j) {
            int row = j * 8 + w;
            float4 v = *(const float4*)(X + (blockRow + row) * 128 + lane * 4);
            float sq = v.x*v.x + v.y*v.y + v.z*v.z + v.w*v.w;
            #pragma unroll
            for (int o = 16; o; o >>= 1) sq += __shfl_xor_sync(0xffffffffu, sq, o);
            if (lane == 0) xn2[row] = sq;
            __nv_bfloat16 h0 = __float2bfloat16(v.x), h1 = __float2bfloat16(v.y);
            __nv_bfloat16 h2 = __float2bfloat16(v.z), h3 = __float2bfloat16(v.w);
            __nv_bfloat16 l0 = __float2bfloat16(v.x - __bfloat162float(h0));
            __nv_bfloat16 l1 = __float2bfloat16(v.y - __bfloat162float(h1));
            __nv_bfloat16 l2 = __float2bfloat16(v.z - __bfloat162float(h2));
            __nv_bfloat16 l3 = __float2bfloat16(v.w - __bfloat162float(h3));
            uint2 ph, pl;
            ph.x = bfu(h0) | (bfu(h1) << 16); ph.y = bfu(h2) | (bfu(h3) << 16);
            pl.x = bfu(l0) | (bfu(l1) << 16); pl.y = bfu(l2) | (bfu(l3) << 16);
            *(uint2*)(xs_hi + row * SM_STRIDE + lane * 4) = ph;
            *(uint2*)(xs_lo + row * SM_STRIDE + lane * 4) = pl;
        }
        __syncthreads();

        // L2 prefetch of next tile's x (no register cost; overlaps MMA)
        {
            int nt2 = tile + gridDim.x;
            if (nt2 < nTiles) {
                const float* pf = X + (size_t)nt2 * 64 * 128 + (size_t)tid * 32;
                asm volatile("prefetch.global.L2 [%0];" :: "l"(pf));
            }
        }

        // ---- MMA: bf16x2 split (hi*hi + hi*lo + lo*hi) ----
        float acc[2][4][4];
        #pragma unroll
        for (int mt = 0; mt < 2; ++mt)
            #pragma unroll
            for (int nt = 0; nt < 4; ++nt)
                #pragma unroll
                for (int r = 0; r < 4; ++r) acc[mt][nt][r] = 0.f;

        #pragma unroll
        for (int k = 0; k < 8; ++k) {
            const uint32_t kb = k * 32;
            uint32_t ah0[4], ah1[4], al0[4], al1[4];
            LDSM4(ah0, s_xhi + aoff0 + kb);
            LDSM4(ah1, s_xhi + aoff1 + kb);
            LDSM4(al0, s_xlo + aoff0 + kb);
            LDSM4(al1, s_xlo + aoff1 + kb);
            uint32_t bh[2][4], bl[2][4];
            #pragma unroll
            for (int p = 0; p < 2; ++p) {
                LDSM4(bh[p], s_whi + boff[p] + kb);
                LDSM4(bl[p], s_wlo + boff[p] + kb);
            }
            #pragma unroll
            for (int nt = 0; nt < 4; ++nt) {
                const int p = nt >> 1, o = (nt & 1) * 2;
                mma16816(acc[0][nt], ah0, &bh[p][o]);
                mma16816(acc[1][nt], ah1, &bh[p][o]);
                mma16816(acc[0][nt], ah0, &bl[p][o]);
                mma16816(acc[1][nt], ah1, &bl[p][o]);
                mma16816(acc[0][nt], al0, &bh[p][o]);
                mma16816(acc[1][nt], al1, &bh[p][o]);
            }
        }

        // ---- phase 1: per-row sum(mx^2), sum(mx*h) ----
        #pragma unroll
        for (int mt = 0; mt < 2; ++mt)
            #pragma unroll
            for (int rh = 0; rh < 2; ++rh) {
                float sq = 0.f, dh = 0.f;
                #pragma unroll
                for (int nt = 0; nt < 4; ++nt) {
                    float v0 = acc[mt][nt][2*rh], v1 = acc[mt][nt][2*rh + 1];
                    sq = fmaf(v0, v0, fmaf(v1, v1, sq));
                    dh = fmaf(v0, hv[nt][0], fmaf(v1, hv[nt][1], dh));
                }
                sq += __shfl_xor_sync(0xffffffffu, sq, 1);
                sq += __shfl_xor_sync(0xffffffffu, sq, 2);
                dh += __shfl_xor_sync(0xffffffffu, dh, 1);
                dh += __shfl_xor_sync(0xffffffffu, dh, 2);
                if (tq == 0) {
                    int r = 32*wm + 16*mt + 8*rh + q;
                    red_sq[wn*64 + r] = sq;
                    red_dh[wn*64 + r] = dh;
                }
            }
        __syncthreads();

        // ---- per-row scalar chain ----
        if (tid < 64) {
            int r = tid;
            float S2 = red_sq[r] + red_sq[64 + r] + red_sq[128 + r] + red_sq[192 + r];
            float D  = red_dh[r] + red_dh[64 + r] + red_dh[128 + r] + red_dh[192 + r];
            float y2 = SC[0];
            float xn  = fmaxf(sqrtf(xn2[r]), MINN);
            float mxn = fmaxf(sqrtf(S2), MINN);
            float atx = artanh_c(xn);
            float r1  = tanhf(mxn / xn * atx);
            float scale1 = r1 / mxn;
            float resn = r1;
            float pn = fmaxf(resn, MINN);
            if (pn > MAXN) { scale1 *= MAXN / pn; resn = MAXN; }
            float x2 = resn * resn;
            float xy = scale1 * D;
            float num1 = 1.f + 2.f*xy + y2;
            float den  = fmaxf(1.f + 2.f*xy + x2*y2, MINN);
            float aC = num1 / den;
            float bC = (1.f - x2) / den;
            float o2n2 = aC*aC*x2 + 2.f*aC*bC*xy + bC*bC*y2;
            float o2n  = sqrtf(fmaxf(o2n2, 0.f));
            float g = 1.f;
            float pn2 = fmaxf(o2n, MINN);
            if (pn2 > MAXN) { g = MAXN / pn2; pn2 = MAXN; }
            float Lr = artanh_c(pn2) / pn2;
            PA[r]  = g * aC * scale1;
            PB[r]  = g * bC;
            LLs[r] = Lr;
        }
        __syncthreads();

        // ---- phase 2: val = Pa*mx + Pb*h ; sum(max(val,0)^2) ----
        #pragma unroll
        for (int mt = 0; mt < 2; ++mt)
            #pragma unroll
            for (int rh = 0; rh < 2; ++rh) {
                int rl = 32*wm + 16*mt + 8*rh + q;
                float pa = PA[rl], pb = PB[rl];
                float ps = 0.f;
                #pragma unroll
                for (int nt = 0; nt < 4; ++nt) {
                    float v0 = fmaf(pa, acc[mt][nt][2*rh],     pb * hv[nt][0]);
                    float v1 = fmaf(pa, acc[mt][nt][2*rh + 1], pb * hv[nt][1]);
                    acc[mt][nt][2*rh]     = v0;
                    acc[mt][nt][2*rh + 1] = v1;
                    float p0 = fmaxf(v0, 0.f), p1 = fmaxf(v1, 0.f);
                    ps = fmaf(p0, p0, fmaf(p1, p1, ps));
                }
                ps += __shfl_xor_sync(0xffffffffu, ps, 1);
                ps += __shfl_xor_sync(0xffffffffu, ps, 2);
                if (tq == 0) red_sq[wn*64 + rl] = ps;
            }
        __syncthreads();

        // ---- phase 3: expmap0 + final proj scale ----
        if (tid < 64) {
            int r = tid;
            float ps = red_sq[r] + red_sq[64 + r] + red_sq[128 + r] + red_sq[192 + r];
            float P  = sqrtf(fmaxf(ps, 0.f));
            float Lr = LLs[r];
            float un = fmaxf(Lr * P, MINN);
            float th = tanhf(un);
            float f  = th / un * Lr;
            if (th > MAXN) f *= MAXN / th;
            FSs[r] = f;
        }
        __syncthreads();

        // ---- store: out = fs * max(val, 0) ----
        #pragma unroll
        for (int mt = 0; mt < 2; ++mt)
            #pragma unroll
            for (int rh = 0; rh < 2; ++rh) {
                int rl = 32*wm + 16*mt + 8*rh + q;
                float fsv = FSs[rl];
                float* outp = OUT + (blockRow + rl) * 128 + 32*wn + 2*tq;
                #pragma unroll
                for (int nt = 0; nt < 4; ++nt) {
                    float2 o;
                    o.x = fsv * fmaxf(acc[mt][nt][2*rh],     0.f);
                    o.y = fsv * fmaxf(acc[mt][nt][2*rh + 1], 0.f);
                    *(float2*)(outp + 8*nt) = o;
                }
            }
        __syncthreads();   // protect xs / xn2 / FSs before next iteration
    }
}

extern "C" void kernel_launch(void* const* d_in, const int* in_sizes, int n_in,
                              void* d_out, int out_size) {
    const float* x = (const float*)d_in[0];
    const float* W = (const float*)d_in[1];
    const float* b = (const float*)d_in[2];
    float* out = (float*)d_out;

    int nRows  = in_sizes[0] / 128;      // 524288
    int nTiles = nRows / 64;             // 8192
    int grid   = 296;                    // 2 CTAs per SM, persistent
    if (grid > nTiles) grid = nTiles;

    cudaFuncSetAttribute(blinear_fused,
                         cudaFuncAttributeMaxDynamicSharedMemorySize, SMEM_BYTES);
    blinear_fused<<<grid, 256, SMEM_BYTES>>>(x, W, b, out, nTiles);
}

// round 3
// speedup vs baseline: 1.4580x; 1.1071x over previous
#include <cuda_runtime.h>
#include <cuda_bf16.h>
#include <cstdint>

#define SM_STRIDE 136            // bf16 elems per smem row (conflict-free ldmatrix)

// smem byte offsets
#define WHI_OFF   0
#define WLO_OFF   (WHI_OFF + 128 * SM_STRIDE * 2)
#define XHI_OFF   (WLO_OFF + 128 * SM_STRIDE * 2)
#define XLO_OFF   (XHI_OFF + 64 * SM_STRIDE * 2)
#define XN2_OFF   (XLO_OFF + 64 * SM_STRIDE * 2)   // float[64]
#define HV_OFF    (XN2_OFF + 256)                  // float[128]
#define RED1_OFF  (HV_OFF  + 512)                  // float4[4][2][8] = 1024 B
#define RED2_OFF  (RED1_OFF + 1024)                // float2[4][2][8] = 512 B
#define SC_OFF    (RED2_OFF + 512)                 // float[4]
#define SMEM_BYTES (SC_OFF + 16)                   // ~104.3 KB -> 2 CTAs/SM

#define MINN  1e-15f
#define MAXN  0.996f
#define ATLIM (1.0f - 1e-7f)

__device__ __forceinline__ unsigned int bfu(__nv_bfloat16 h) {
    return (unsigned int)*reinterpret_cast<unsigned short*>(&h);
}

#define LDSM4(R, addr)                                                        \
    asm volatile("ldmatrix.sync.aligned.m8n8.x4.shared.b16 {%0,%1,%2,%3}, [%4];" \
                 : "=r"((R)[0]), "=r"((R)[1]), "=r"((R)[2]), "=r"((R)[3])     \
                 : "r"(addr) : "memory")

#define PAIR_BAR() asm volatile("bar.sync %0, 64;" :: "r"(barid) : "memory")

__device__ __forceinline__ void mma16816(float* d, const uint32_t* a, const uint32_t* b) {
    asm volatile(
        "mma.sync.aligned.m16n8k16.row.col.f32.bf16.bf16.f32 "
        "{%0,%1,%2,%3}, {%4,%5,%6,%7}, {%8,%9}, {%0,%1,%2,%3};"
        : "+f"(d[0]), "+f"(d[1]), "+f"(d[2]), "+f"(d[3])
        : "r"(a[0]), "r"(a[1]), "r"(a[2]), "r"(a[3]), "r"(b[0]), "r"(b[1]));
}

__device__ __forceinline__ float artanh_c(float x) {
    float xc = fminf(x, ATLIM);
    return 0.5f * (log1pf(xc) - log1pf(-xc));
}

// per-row chain: (S2, D, xn2, y2) -> pa, pb, Lr
__device__ __forceinline__ void row_chain(float S2, float D, float xn2v, float y2,
                                          float& pa, float& pb, float& Lr) {
    float xn  = fmaxf(sqrtf(xn2v), MINN);
    float mxn = fmaxf(sqrtf(S2), MINN);
    float atx = artanh_c(xn);
    float r1  = tanhf(mxn / xn * atx);
    float scale1 = r1 / mxn;
    float resn = r1;
    float pn = fmaxf(resn, MINN);
    if (pn > MAXN) { scale1 *= MAXN / pn; resn = MAXN; }
    float x2 = resn * resn;
    float xy = scale1 * D;
    float num1 = 1.f + 2.f*xy + y2;
    float den  = fmaxf(1.f + 2.f*xy + x2*y2, MINN);
    float aC = num1 / den;
    float bC = (1.f - x2) / den;
    float o2n2 = aC*aC*x2 + 2.f*aC*bC*xy + bC*bC*y2;
    float o2n  = sqrtf(fmaxf(o2n2, 0.f));
    float g = 1.f;
    float pn2 = fmaxf(o2n, MINN);
    if (pn2 > MAXN) { g = MAXN / pn2; pn2 = MAXN; }
    Lr = artanh_c(pn2) / pn2;
    pa = g * aC * scale1;
    pb = g * bC;
}

__device__ __forceinline__ float final_scale(float ps, float Lr) {
    float P  = sqrtf(fmaxf(ps, 0.f));
    float un = fmaxf(Lr * P, MINN);
    float th = tanhf(un);
    float f  = th / un * Lr;
    if (th > MAXN) f *= MAXN / th;
    return f;
}

__global__ void __launch_bounds__(256, 2)
blinear_fused(const float* __restrict__ X, const float* __restrict__ W,
              const float* __restrict__ B, float* __restrict__ OUT, int nTiles)
{
    extern __shared__ char smem[];
    __nv_bfloat16* ws_hi = (__nv_bfloat16*)(smem + WHI_OFF);
    __nv_bfloat16* ws_lo = (__nv_bfloat16*)(smem + WLO_OFF);
    __nv_bfloat16* xs_hi = (__nv_bfloat16*)(smem + XHI_OFF);
    __nv_bfloat16* xs_lo = (__nv_bfloat16*)(smem + XLO_OFF);
    float* xn2_s = (float*)(smem + XN2_OFF);
    float* hvec  = (float*)(smem + HV_OFF);
    float* red1  = (float*)(smem + RED1_OFF);
    float* red2  = (float*)(smem + RED2_OFF);
    float* SC    = (float*)(smem + SC_OFF);

    const int tid  = threadIdx.x;
    const int lane = tid & 31;
    const int w    = tid >> 5;   // 0..7
    const int pr   = w >> 1;     // pair 0..3 : rows 16*pr .. 16*pr+15
    const int wh   = w & 1;      // col half  : cols 64*wh .. 64*wh+63
    const int tq   = lane & 3;
    const int q    = lane >> 2;
    const int barid = 1 + pr;

    // ---- once per CTA: convert W (128x128) to bf16 hi/lo in smem ----
    #pragma unroll
    for (int j = 0; j < 16; ++j) {
        int row = j * 8 + w;
        float4 wv = *(const float4*)(W + (size_t)row * 128 + lane * 4);
        __nv_bfloat16 h0 = __float2bfloat16(wv.x), h1 = __float2bfloat16(wv.y);
        __nv_bfloat16 h2 = __float2bfloat16(wv.z), h3 = __float2bfloat16(wv.w);
        __nv_bfloat16 l0 = __float2bfloat16(wv.x - __bfloat162float(h0));
        __nv_bfloat16 l1 = __float2bfloat16(wv.y - __bfloat162float(h1));
        __nv_bfloat16 l2 = __float2bfloat16(wv.z - __bfloat162float(h2));
        __nv_bfloat16 l3 = __float2bfloat16(wv.w - __bfloat162float(h3));
        uint2 ph, pl;
        ph.x = bfu(h0) | (bfu(h1) << 16); ph.y = bfu(h2) | (bfu(h3) << 16);
        pl.x = bfu(l0) | (bfu(l1) << 16); pl.y = bfu(l2) | (bfu(l3) << 16);
        *(uint2*)(ws_hi + row * SM_STRIDE + lane * 4) = ph;
        *(uint2*)(ws_lo + row * SM_STRIDE + lane * 4) = pl;
    }

    // ---- once per CTA: hyp_bias h = proj(expmap0(b)) (warp 0) ----
    if (w == 0) {
        float4 bv = *(const float4*)(B + lane * 4);
        float sq = bv.x*bv.x + bv.y*bv.y + bv.z*bv.z + bv.w*bv.w;
        #pragma unroll
        for (int o = 16; o; o >>= 1) sq += __shfl_xor_sync(0xffffffffu, sq, o);
        float bn2 = sq;
        float bn  = fmaxf(sqrtf(bn2), MINN);
        float th  = tanhf(bn);
        float hs  = th / bn;
        float hn  = hs * sqrtf(bn2);
        float pn  = fmaxf(hn, MINN);
        if (pn > MAXN) hs *= MAXN / pn;
        float y2v = hs * hs * bn2;
        if (lane == 0) SC[0] = y2v;
        *(float4*)(hvec + lane * 4) =
            make_float4(hs*bv.x, hs*bv.y, hs*bv.z, hs*bv.w);
    }
    __syncthreads();

    const float y2 = SC[0];

    // preload h slice for this warp's 64 columns (constant across tiles)
    float hv[8][2];
    #pragma unroll
    for (int nt = 0; nt < 8; ++nt) {
        int c = 64*wh + 8*nt + 2*tq;
        hv[nt][0] = hvec[c]; hv[nt][1] = hvec[c + 1];
    }

    uint32_t s_xhi = (uint32_t)__cvta_generic_to_shared(xs_hi);
    uint32_t s_xlo = (uint32_t)__cvta_generic_to_shared(xs_lo);
    uint32_t s_whi = (uint32_t)__cvta_generic_to_shared(ws_hi);
    uint32_t s_wlo = (uint32_t)__cvta_generic_to_shared(ws_lo);

    // A fragment address: pair rows 16*pr..16*pr+15
    const uint32_t aoff = (uint32_t)(((16*pr + (lane & 15)) * SM_STRIDE + (lane >> 4) * 8) * 2);
    // B fragment addresses: 4 n16-groups covering this warp's 64 cols
    const int bg  = lane >> 3;
    const int b_n = ((bg >> 1) << 3) + (lane & 7);
    const int b_k = (bg & 1) * 8;
    uint32_t boff[4];
    #pragma unroll
    for (int g = 0; g < 4; ++g)
        boff[g] = (uint32_t)(((64*wh + 16*g + b_n) * SM_STRIDE + b_k) * 2);

    // exchange buffer slots
    float4* r1_me = (float4*)(red1 + ((pr*2 + wh    )*8 + q) * 4);
    float4* r1_ot = (float4*)(red1 + ((pr*2 + (wh^1))*8 + q) * 4);
    float2* r2_me = (float2*)(red2 + ((pr*2 + wh    )*8 + q) * 2);
    float2* r2_ot = (float2*)(red2 + ((pr*2 + (wh^1))*8 + q) * 2);

    const int rl0 = 16*pr + q;       // local tile row for acc elems 0,1
    const int rl1 = rl0 + 8;         // local tile row for acc elems 2,3

    // ================= persistent tile loop =================
    for (int tile = blockIdx.x; tile < nTiles; tile += gridDim.x) {
        const size_t tileRow = (size_t)tile * 64;

        // ---- load this warp's 8 rows (full 128 cols), norms, bf16 split ----
        #pragma unroll
        for (int j = 0; j < 8; ++j) {
            int rloc = 16*pr + 8*wh + j;
            float4 v = *(const float4*)(X + (tileRow + rloc) * 128 + lane * 4);
            float sq = v.x*v.x + v.y*v.y + v.z*v.z + v.w*v.w;
            #pragma unroll
            for (int o = 16; o; o >>= 1) sq += __shfl_xor_sync(0xffffffffu, sq, o);
            if (lane == 0) xn2_s[rloc] = sq;
            __nv_bfloat16 h0 = __float2bfloat16(v.x), h1 = __float2bfloat16(v.y);
            __nv_bfloat16 h2 = __float2bfloat16(v.z), h3 = __float2bfloat16(v.w);
            __nv_bfloat16 l0 = __float2bfloat16(v.x - __bfloat162float(h0));
            __nv_bfloat16 l1 = __float2bfloat16(v.y - __bfloat162float(h1));
            __nv_bfloat16 l2 = __float2bfloat16(v.z - __bfloat162float(h2));
            __nv_bfloat16 l3 = __float2bfloat16(v.w - __bfloat162float(h3));
            uint2 ph, pl;
            ph.x = bfu(h0) | (bfu(h1) << 16); ph.y = bfu(h2) | (bfu(h3) << 16);
            pl.x = bfu(l0) | (bfu(l1) << 16); pl.y = bfu(l2) | (bfu(l3) << 16);
            *(uint2*)(xs_hi + rloc * SM_STRIDE + lane * 4) = ph;
            *(uint2*)(xs_lo + rloc * SM_STRIDE + lane * 4) = pl;
        }

        // L2 prefetch next tile's rows for this warp (8 rows = 4 KB = 32 lines)
        {
            int nt2 = tile + gridDim.x;
            if (nt2 < nTiles) {
                const float* pf = X + ((size_t)nt2 * 64 + 16*pr + 8*wh) * 128
                                    + (size_t)lane * 32;
                asm volatile("prefetch.global.L2 [%0];" :: "l"(pf));
            }
        }

        PAIR_BAR();   // xs + xn2 visible within pair

        // ---- MMA: bf16x2 split (hi*hi + hi*lo + lo*hi) ----
        float acc[8][4];
        #pragma unroll
        for (int nt = 0; nt < 8; ++nt)
            #pragma unroll
            for (int r = 0; r < 4; ++r) acc[nt][r] = 0.f;

        #pragma unroll
        for (int k = 0; k < 8; ++k) {
            const uint32_t kb = k * 32;
            uint32_t ah[4], al[4];
            LDSM4(ah, s_xhi + aoff + kb);
            LDSM4(al, s_xlo + aoff + kb);
            uint32_t bh[4][4], bl[4][4];
            #pragma unroll
            for (int g = 0; g < 4; ++g) {
                LDSM4(bh[g], s_whi + boff[g] + kb);
                LDSM4(bl[g], s_wlo + boff[g] + kb);
            }
            #pragma unroll
            for (int nt = 0; nt < 8; ++nt) {
                const int g = nt >> 1, o = (nt & 1) * 2;
                mma16816(acc[nt], ah, &bh[g][o]);
                mma16816(acc[nt], ah, &bl[g][o]);
                mma16816(acc[nt], al, &bh[g][o]);
            }
        }

        // ---- phase 1: per-row sum(mx^2), sum(mx*h) over this warp's 64 cols ----
        float sq0 = 0.f, dh0 = 0.f, sq1 = 0.f, dh1 = 0.f;
        #pragma unroll
        for (int nt = 0; nt < 8; ++nt) {
            float v0 = acc[nt][0], v1 = acc[nt][1];
            float v2 = acc[nt][2], v3 = acc[nt][3];
            sq0 = fmaf(v0, v0, fmaf(v1, v1, sq0));
            dh0 = fmaf(v0, hv[nt][0], fmaf(v1, hv[nt][1], dh0));
            sq1 = fmaf(v2, v2, fmaf(v3, v3, sq1));
            dh1 = fmaf(v2, hv[nt][0], fmaf(v3, hv[nt][1], dh1));
        }
        #pragma unroll
        for (int o = 1; o <= 2; o <<= 1) {
            sq0 += __shfl_xor_sync(0xffffffffu, sq0, o);
            dh0 += __shfl_xor_sync(0xffffffffu, dh0, o);
            sq1 += __shfl_xor_sync(0xffffffffu, sq1, o);
            dh1 += __shfl_xor_sync(0xffffffffu, dh1, o);
        }
        if (tq == 0) *r1_me = make_float4(sq0, dh0, sq1, dh1);
        PAIR_BAR();
        float4 ot = *r1_ot;
        float S2_0 = sq0 + ot.x, D0 = dh0 + ot.y;
        float S2_1 = sq1 + ot.z, D1 = dh1 + ot.w;

        // ---- per-row scalar chain (in registers, per-quad redundant) ----
        float pa0, pb0, Lr0, pa1, pb1, Lr1;
        row_chain(S2_0, D0, xn2_s[rl0], y2, pa0, pb0, Lr0);
        row_chain(S2_1, D1, xn2_s[rl1], y2, pa1, pb1, Lr1);

        // ---- phase 2: val = pa*mx + pb*h ; sum(relu(val)^2) ----
        float ps0 = 0.f, ps1 = 0.f;
        #pragma unroll
        for (int nt = 0; nt < 8; ++nt) {
            float v0 = fmaf(pa0, acc[nt][0], pb0 * hv[nt][0]);
            float v1 = fmaf(pa0, acc[nt][1], pb0 * hv[nt][1]);
            float v2 = fmaf(pa1, acc[nt][2], pb1 * hv[nt][0]);
            float v3 = fmaf(pa1, acc[nt][3], pb1 * hv[nt][1]);
            acc[nt][0] = v0; acc[nt][1] = v1; acc[nt][2] = v2; acc[nt][3] = v3;
            float p0 = fmaxf(v0, 0.f), p1 = fmaxf(v1, 0.f);
            float p2 = fmaxf(v2, 0.f), p3 = fmaxf(v3, 0.f);
            ps0 = fmaf(p0, p0, fmaf(p1, p1, ps0));
            ps1 = fmaf(p2, p2, fmaf(p3, p3, ps1));
        }
        #pragma unroll
        for (int o = 1; o <= 2; o <<= 1) {
            ps0 += __shfl_xor_sync(0xffffffffu, ps0, o);
            ps1 += __shfl_xor_sync(0xffffffffu, ps1, o);
        }
        if (tq == 0) *r2_me = make_float2(ps0, ps1);
        PAIR_BAR();
        float2 ot2 = *r2_ot;
        float fs0 = final_scale(ps0 + ot2.x, Lr0);
        float fs1 = final_scale(ps1 + ot2.y, Lr1);

        // ---- store: out = fs * relu(val) ----
        float* outp = OUT + (tileRow + rl0) * 128 + 64*wh + 2*tq;
        #pragma unroll
        for (int nt = 0; nt < 8; ++nt) {
            float2 o0, o1;
            o0.x = fs0 * fmaxf(acc[nt][0], 0.f);
            o0.y = fs0 * fmaxf(acc[nt][1], 0.f);
            o1.x = fs1 * fmaxf(acc[nt][2], 0.f);
            o1.y = fs1 * fmaxf(acc[nt][3], 0.f);
            *(float2*)(outp + 8*nt)        = o0;
            *(float2*)(outp + 1024 + 8*nt) = o1;   // row rl1 = rl0 + 8
        }
        // cross-iteration smem reuse is ordered by the three pair barriers
    }
}

extern "C" void kernel_launch(void* const* d_in, const int* in_sizes, int n_in,
                              void* d_out, int out_size) {
    const float* x = (const float*)d_in[0];
    const float* W = (const float*)d_in[1];
    const float* b = (const float*)d_in[2];
    float* out = (float*)d_out;

    int nRows  = in_sizes[0] / 128;      // 524288
    int nTiles = nRows / 64;             // 8192
    int grid   = 296;                    // 2 CTAs per SM, persistent
    if (grid > nTiles) grid = nTiles;

    cudaFuncSetAttribute(blinear_fused,
                         cudaFuncAttributeMaxDynamicSharedMemorySize, SMEM_BYTES);
    blinear_fused<<<grid, 256, SMEM_BYTES>>>(x, W, b, out, nTiles);
}